// round 5
// baseline (speedup 1.0000x reference)
#include <cuda_runtime.h>
#include <cuda_bf16.h>
#include <math.h>
#include <stdint.h>

#define TT 8
#define NNODE 40000
#define FF 256
#define PP 128
#define GG 128
#define HH 128
#define BB 1024
#define NE 640000
#define NNZ (NE + NNODE)

// ------------------------- device scratch -------------------------
__device__ __align__(16) float g_h  [(size_t)NNODE * PP];
__device__ __align__(16) float g_m  [(size_t)NNODE * GG];
__device__ __align__(16) float g_h1 [(size_t)NNODE * GG];
__device__ __align__(16) float g_h2 [(size_t)NNODE * GG];
__device__ __align__(16) float g_hc [(size_t)NNODE * GG];
__device__ __align__(16) float g_mc [(size_t)NNODE * GG];
__device__ __align__(16) float g_tgt[(size_t)TT * BB * (2 * GG)];
__device__ __align__(16) float g_gi [(size_t)TT * BB * (3 * HH)];
__device__ __align__(16) float g_gh [(size_t)BB * (3 * HH)];
__device__ __align__(16) float g_gruh[(size_t)BB * HH];
__device__ __align__(16) float g_outs[(size_t)TT * BB * HH];
__device__ __align__(16) float g_val [NNZ];
__device__ __align__(16) float g_dinv[NNODE];
__device__ __align__(16) int   g_col [NNZ];
__device__ __align__(16) int   g_rowptr[NNODE + 1];
__device__ __align__(16) int   g_deg [NNODE];
__device__ __align__(16) int   g_fill[NNODE];
__device__ __align__(16) int   g_src [NE];
__device__ __align__(16) int   g_dst [NE];
__device__ __align__(16) int   g_ti  [BB];
// pruning structures
__device__ __align__(16) int   g_tmask[NNODE];
__device__ __align__(16) int   g_smask[NNODE];
__device__ __align__(16) int   g_snodes[NNODE];
__device__ __align__(16) int   g_sidx [NNODE];
__device__ __align__(16) int   g_tnodes[BB];
__device__ int g_nt;
__device__ int g_ns;
__device__ int g_is64;
// permuted tf32 weights (fragment-linear order)
__device__ __align__(16) uint32_t g_pw  [256 * 128];
__device__ __align__(16) uint32_t g_pw1 [128 * 128];
__device__ __align__(16) uint32_t g_pw2 [128 * 128];
__device__ __align__(16) uint32_t g_pwih[256 * 384];
__device__ __align__(16) uint32_t g_pwhh[128 * 384];

// ------------------------- tf32 helpers -------------------------
__device__ __forceinline__ uint32_t f2tf(float f) {
    uint32_t r;
    asm("cvt.rna.tf32.f32 %0, %1;" : "=r"(r) : "f"(f));
    return r;
}
__device__ __forceinline__ void mma8(float* c, const uint32_t* a, const uint32_t* b) {
    asm volatile(
        "mma.sync.aligned.m16n8k8.row.col.f32.tf32.tf32.f32 "
        "{%0,%1,%2,%3},{%4,%5,%6,%7},{%8,%9},{%0,%1,%2,%3};"
        : "+f"(c[0]), "+f"(c[1]), "+f"(c[2]), "+f"(c[3])
        : "r"(a[0]), "r"(a[1]), "r"(a[2]), "r"(a[3]), "r"(b[0]), "r"(b[1]));
}

// ------------------------- weight permutation to fragment order -------------------------
// out[((nb*K8 + kg)*16 + nt)*64 + lane*2 + j] = tf32(W[k][n]),
//   k = kg*8 + (lane&3) + 4*j,  n = nb*128 + nt*8 + (lane>>2)
template<bool TRANS>
__global__ void k_permB(const float* __restrict__ W, uint32_t* __restrict__ out, int K, int N) {
    int i = blockIdx.x * blockDim.x + threadIdx.x;
    if (i >= K * N) return;
    int tmp = i;
    int j = tmp & 1;       tmp >>= 1;
    int lane = tmp & 31;   tmp >>= 5;
    int nt = tmp & 15;     tmp >>= 4;
    int K8 = K >> 3;
    int kg = tmp % K8;
    int nb = tmp / K8;
    int k = kg * 8 + (lane & 3) + 4 * j;
    int n = nb * 128 + nt * 8 + (lane >> 2);
    float v = TRANS ? W[(size_t)n * K + k] : W[(size_t)k * N + n];
    out[i] = f2tf(v);
}

// ------------------------- TF32 GEMM: C[M,N] = op(A @ B + bias) -------------------------
// CTA: 128x128, 8 warps (warpM 0..3 x 32 rows, warpN 0..1 x 64 cols), KTOT compile-time.
// ASEL: 0 ext, 1 g_h, 2 g_hc, 3 g_tgt, 4 g_gruh ; CSEL: 1 g_h, 2 g_m, 3 g_mc, 4 g_gi, 5 g_gh
// MSEL: 0 = param M, 1 = g_ns
template<int KTOT, int ASEL, int CSEL, int MSEL, bool RELU, bool BIAS>
__global__ void __launch_bounds__(256) tfgemm(const float* __restrict__ Aext,
                                              const uint32_t* __restrict__ pB,
                                              const float* __restrict__ bias, int Mparam)
{
    int M = (MSEL == 1) ? g_ns : Mparam;
    int rowBase = blockIdx.y * 128;
    if (rowBase >= M) return;

    const float* A;
    if constexpr (ASEL == 1)      A = g_h;
    else if constexpr (ASEL == 2) A = g_hc;
    else if constexpr (ASEL == 3) A = g_tgt;
    else if constexpr (ASEL == 4) A = g_gruh;
    else                          A = Aext;
    float* C;
    if constexpr (CSEL == 1)      C = g_h;
    else if constexpr (CSEL == 2) C = g_m;
    else if constexpr (CSEL == 3) C = g_mc;
    else if constexpr (CSEL == 4) C = g_gi;
    else                          C = g_gh;

    const int K8 = KTOT / 8;
    const int N = gridDim.x * 128;
    const int nb = blockIdx.x;

    __shared__ __align__(16) uint32_t As[16 * 128];   // 16 tiles x 128 (fragment order)

    int tid = threadIdx.x;
    int lane = tid & 31;
    int w = tid >> 5;
    int warpM = w & 3;
    int warpN = w >> 2;

    float acc[2][8][4];
#pragma unroll
    for (int mt = 0; mt < 2; mt++)
#pragma unroll
        for (int nt = 0; nt < 8; nt++)
#pragma unroll
            for (int q = 0; q < 4; q++) acc[mt][nt][q] = 0.f;

    // loader indices
    int r_local = tid >> 1;          // 0..127
    int ksl = tid & 1;               // 0..1
    int gr = rowBase + r_local;
    int rr = r_local & 15;
    int mtg = r_local >> 4;
    int stile = mtg * 2 + ksl;
    int sbase = stile * 128;
    int lane4 = (rr & 7) * 4;
    int slot = rr >> 3;

    for (int kc = 0; kc < KTOT / 16; kc++) {
        int k0 = kc * 16 + ksl * 8;
        float4 v0 = make_float4(0.f, 0.f, 0.f, 0.f);
        float4 v1 = make_float4(0.f, 0.f, 0.f, 0.f);
        if (gr < M) {
            const float4* src = (const float4*)(A + (size_t)gr * KTOT + k0);
            v0 = src[0];
            v1 = src[1];
        }
        if (kc > 0) __syncthreads();
        As[sbase + (lane4 + 0) * 4 + slot] = f2tf(v0.x);
        As[sbase + (lane4 + 1) * 4 + slot] = f2tf(v0.y);
        As[sbase + (lane4 + 2) * 4 + slot] = f2tf(v0.z);
        As[sbase + (lane4 + 3) * 4 + slot] = f2tf(v0.w);
        As[sbase + (lane4 + 0) * 4 + slot + 2] = f2tf(v1.x);
        As[sbase + (lane4 + 1) * 4 + slot + 2] = f2tf(v1.y);
        As[sbase + (lane4 + 2) * 4 + slot + 2] = f2tf(v1.z);
        As[sbase + (lane4 + 3) * 4 + slot + 2] = f2tf(v1.w);
        __syncthreads();

#pragma unroll
        for (int ks = 0; ks < 2; ks++) {
            int kg = kc * 2 + ks;
            uint32_t af[2][4];
#pragma unroll
            for (int mt = 0; mt < 2; mt++) {
                uint4 t = *(const uint4*)&As[((warpM * 2 + mt) * 2 + ks) * 128 + lane * 4];
                af[mt][0] = t.x; af[mt][1] = t.y; af[mt][2] = t.z; af[mt][3] = t.w;
            }
#pragma unroll
            for (int nt = 0; nt < 8; nt++) {
                int ntg = warpN * 8 + nt;
                uint2 b = *(const uint2*)&pB[(((size_t)nb * K8 + kg) * 16 + ntg) * 64 + lane * 2];
                uint32_t bb[2] = {b.x, b.y};
                mma8(acc[0][nt], af[0], bb);
                mma8(acc[1][nt], af[1], bb);
            }
        }
    }

    // epilogue
#pragma unroll
    for (int mt = 0; mt < 2; mt++) {
        int r0 = rowBase + warpM * 32 + mt * 16 + (lane >> 2);
        int r1 = r0 + 8;
#pragma unroll
        for (int nt = 0; nt < 8; nt++) {
            int cb = nb * 128 + warpN * 64 + nt * 8 + (lane & 3) * 2;
            float o0 = acc[mt][nt][0], o1 = acc[mt][nt][1];
            float o2 = acc[mt][nt][2], o3 = acc[mt][nt][3];
            if (BIAS) {
                float b0 = bias[cb], b1 = bias[cb + 1];
                o0 += b0; o1 += b1; o2 += b0; o3 += b1;
            }
            if (RELU) {
                o0 = fmaxf(o0, 0.f); o1 = fmaxf(o1, 0.f);
                o2 = fmaxf(o2, 0.f); o3 = fmaxf(o3, 0.f);
            }
            if (r0 < M) { float2 s = {o0, o1}; *(float2*)(C + (size_t)r0 * N + cb) = s; }
            if (r1 < M) { float2 s = {o2, o3}; *(float2*)(C + (size_t)r1 * N + cb) = s; }
        }
    }
}

// ------------------------- index dtype detection + conversion -------------------------
__global__ void k_detect(const unsigned int* __restrict__ wdata, int n_elems) {
    __shared__ int bad;
    if (threadIdx.x == 0) bad = 0;
    __syncthreads();
    int limit = n_elems < 4096 ? n_elems : 4096;
    for (int i = threadIdx.x; i < limit; i += blockDim.x)
        if (wdata[2 * i + 1] != 0u) bad = 1;
    __syncthreads();
    if (threadIdx.x == 0) g_is64 = bad ? 0 : 1;
}

__device__ __forceinline__ int clampN(int v) {
    return v < 0 ? 0 : (v >= NNODE ? NNODE - 1 : v);
}

__global__ void k_cvt_edges(const void* __restrict__ ei) {
    int e = blockIdx.x * blockDim.x + threadIdx.x;
    if (e < NE) {
        int s, d;
        if (g_is64) {
            const long long* p = (const long long*)ei;
            s = (int)p[e]; d = (int)p[NE + e];
        } else {
            const int* p = (const int*)ei;
            s = p[e]; d = p[NE + e];
        }
        g_src[e] = clampN(s);
        g_dst[e] = clampN(d);
    }
}

__global__ void k_cvt_ti(const void* __restrict__ ti) {
    int b = blockIdx.x * blockDim.x + threadIdx.x;
    if (b < BB) {
        int v;
        if (g_is64) v = (int)((const long long*)ti)[b];
        else        v = ((const int*)ti)[b];
        g_ti[b] = clampN(v);
    }
}

// ------------------------- graph preprocessing -------------------------
__global__ void k_init_deg() {
    int i = blockIdx.x * blockDim.x + threadIdx.x;
    if (i < NNODE) { g_deg[i] = 1; g_fill[i] = 0; }
    if (i == 0) { g_nt = 0; g_ns = 0; }
}

__global__ void k_deg_edges() {
    int e = blockIdx.x * blockDim.x + threadIdx.x;
    if (e < NE) atomicAdd(&g_deg[g_dst[e]], 1);
}

__global__ void k_dinv() {
    int i = blockIdx.x * blockDim.x + threadIdx.x;
    if (i < NNODE) g_dinv[i] = rsqrtf((float)g_deg[i]);
}

__global__ void k_scan() {
    const int CH = 40;
    int t = threadIdx.x;
    int lane = t & 31, wid = t >> 5;
    int beg = t * CH;
    int sum = 0;
    for (int i = 0; i < CH; i++) {
        int idx = beg + i;
        if (idx < NNODE) sum += g_deg[idx];
    }
    int v = sum;
    for (int o = 1; o < 32; o <<= 1) {
        int u = __shfl_up_sync(0xffffffffu, v, o);
        if (lane >= o) v += u;
    }
    __shared__ int wsum[32];
    if (lane == 31) wsum[wid] = v;
    __syncthreads();
    if (wid == 0) {
        int w = wsum[lane];
        for (int o = 1; o < 32; o <<= 1) {
            int u = __shfl_up_sync(0xffffffffu, w, o);
            if (lane >= o) w += u;
        }
        wsum[lane] = w;
    }
    __syncthreads();
    int run = v - sum + (wid > 0 ? wsum[wid - 1] : 0);
    for (int i = 0; i < CH; i++) {
        int idx = beg + i;
        if (idx < NNODE) {
            g_rowptr[idx] = run;
            run += g_deg[idx];
        }
    }
    if (t == 1023) g_rowptr[NNODE] = run;
}

__global__ void k_selfloop() {
    int n = blockIdx.x * blockDim.x + threadIdx.x;
    if (n < NNODE) {
        int pos = g_rowptr[n];
        g_col[pos] = n;
        float d = g_dinv[n];
        g_val[pos] = d * d;
        g_fill[n] = 1;
    }
}

__global__ void k_fill_edges() {
    int e = blockIdx.x * blockDim.x + threadIdx.x;
    if (e < NE) {
        int s = g_src[e];
        int d = g_dst[e];
        int pos = g_rowptr[d] + atomicAdd(&g_fill[d], 1);
        g_col[pos] = s;
        g_val[pos] = g_dinv[s] * g_dinv[d];
    }
}

// ------------------------- target-neighborhood compaction -------------------------
__global__ void k_clear_masks() {
    int i = blockIdx.x * blockDim.x + threadIdx.x;
    if (i < NNODE) { g_tmask[i] = 0; g_smask[i] = 0; }
}
__global__ void k_mark_t() {
    int b = blockIdx.x * blockDim.x + threadIdx.x;
    if (b < BB) g_tmask[g_ti[b]] = 1;
}
__global__ void k_mark_s() {
    int e = blockIdx.x * blockDim.x + threadIdx.x;
    if (e < NE && g_tmask[g_dst[e]]) g_smask[g_src[e]] = 1;
}
__global__ void k_mark_s2() {
    int n = blockIdx.x * blockDim.x + threadIdx.x;
    if (n < NNODE && g_tmask[n]) g_smask[n] = 1;
}
__global__ void k_compact() {
    int n = blockIdx.x * blockDim.x + threadIdx.x;
    if (n < NNODE) {
        if (g_tmask[n]) g_tnodes[atomicAdd(&g_nt, 1)] = n;
        if (g_smask[n]) {
            int ix = atomicAdd(&g_ns, 1);
            g_snodes[ix] = n;
            g_sidx[n] = ix;
        }
    }
}

// ------------------------- GCN layer-1 aggregation (full graph) -------------------------
__global__ void k_agg1(const float* __restrict__ bias)
{
    int warp = (blockIdx.x * blockDim.x + threadIdx.x) >> 5;
    int lane = threadIdx.x & 31;
    if (warp >= NNODE) return;
    int s0 = g_rowptr[warp], s1 = g_rowptr[warp + 1];
    const float4* m4 = (const float4*)g_m;
    float4 acc = make_float4(0.f, 0.f, 0.f, 0.f);
    for (int e = s0; e < s1; e++) {
        float v = g_val[e];
        float4 t = m4[(size_t)g_col[e] * 32 + lane];
        acc.x = fmaf(v, t.x, acc.x); acc.y = fmaf(v, t.y, acc.y);
        acc.z = fmaf(v, t.z, acc.z); acc.w = fmaf(v, t.w, acc.w);
    }
    int c = lane * 4;
    acc.x = fmaxf(acc.x + bias[c + 0], 0.f);
    acc.y = fmaxf(acc.y + bias[c + 1], 0.f);
    acc.z = fmaxf(acc.z + bias[c + 2], 0.f);
    acc.w = fmaxf(acc.w + bias[c + 3], 0.f);
    ((float4*)g_h1)[(size_t)warp * 32 + lane] = acc;
}

// gather h1 rows of source nodes into compact buffer
__global__ void k_gather_hc() {
    int warp = (blockIdx.x * blockDim.x + threadIdx.x) >> 5;
    int lane = threadIdx.x & 31;
    if (warp >= g_ns) return;
    int row = g_snodes[warp];
    ((float4*)g_hc)[(size_t)warp * 32 + lane] = ((const float4*)g_h1)[(size_t)row * 32 + lane];
}

// layer-2 aggregation only over unique target nodes (compact m)
__global__ void k_agg2t(const float* __restrict__ bias)
{
    int warp = (blockIdx.x * blockDim.x + threadIdx.x) >> 5;
    int lane = threadIdx.x & 31;
    if (warp >= g_nt) return;
    int node = g_tnodes[warp];
    int s0 = g_rowptr[node], s1 = g_rowptr[node + 1];
    const float4* m4 = (const float4*)g_mc;
    float4 acc = make_float4(0.f, 0.f, 0.f, 0.f);
    for (int e = s0; e < s1; e++) {
        float v = g_val[e];
        float4 t = m4[(size_t)g_sidx[g_col[e]] * 32 + lane];
        acc.x = fmaf(v, t.x, acc.x); acc.y = fmaf(v, t.y, acc.y);
        acc.z = fmaf(v, t.z, acc.z); acc.w = fmaf(v, t.w, acc.w);
    }
    int c = lane * 4;
    acc.x = fmaxf(acc.x + bias[c + 0], 0.f);
    acc.y = fmaxf(acc.y + bias[c + 1], 0.f);
    acc.z = fmaxf(acc.z + bias[c + 2], 0.f);
    acc.w = fmaxf(acc.w + bias[c + 3], 0.f);
    ((float4*)g_h2)[(size_t)node * 32 + lane] = acc;
}

// ------------------------- gather targets -------------------------
__global__ void k_gather(int t) {
    int b = blockIdx.x;
    int f = threadIdx.x;                   // 256
    int node = g_ti[b];
    float v = (f < GG) ? g_h1[(size_t)node * GG + f]
                       : g_h2[(size_t)node * GG + (f - GG)];
    g_tgt[((size_t)t * BB + b) * (2 * GG) + f] = v;
}

__global__ void k_zero_h0() {
    int i = blockIdx.x * blockDim.x + threadIdx.x;
    if (i < BB * HH) g_gruh[i] = 0.f;
}

// ------------------------- GRU pointwise -------------------------
__device__ __forceinline__ float sigmoidf_(float x) { return 1.f / (1.f + expf(-x)); }

__global__ void k_gru_pt(int t) {
    int idx = blockIdx.x * blockDim.x + threadIdx.x;
    if (idx >= BB * HH) return;
    int b = idx >> 7, j = idx & 127;
    size_t gir = ((size_t)t * BB + b) * 384;
    size_t ghr = (size_t)b * 384;
    float hr = g_gh[ghr + j], hz = g_gh[ghr + 128 + j], hg = g_gh[ghr + 256 + j];
    float h = g_gruh[idx];
    float r = sigmoidf_(g_gi[gir + j] + hr);
    float z = sigmoidf_(g_gi[gir + 128 + j] + hz);
    float g = tanhf(g_gi[gir + 256 + j] + r * hg);
    float hn = (1.f - z) * g + z * h;
    g_gruh[idx] = hn;
    g_outs[(size_t)t * BB * HH + idx] = hn;
}

// ------------------------- attention + prediction head -------------------------
__global__ void k_final(const float* __restrict__ attn_w, const float* __restrict__ attn_b,
                        const float* __restrict__ pw1, const float* __restrict__ pb1,
                        const float* __restrict__ pw2, const float* __restrict__ pb2,
                        float* __restrict__ out)
{
    int b = blockIdx.x;
    int j = threadIdx.x;                   // 128
    __shared__ float so[TT][HH];
    __shared__ float red[HH];
    __shared__ float sc[TT];
    __shared__ float w8[TT];
    __shared__ float hm[16];

#pragma unroll
    for (int t = 0; t < TT; t++) so[t][j] = g_outs[((size_t)t * BB + b) * HH + j];
    float aw = attn_w[j];
    __syncthreads();

    for (int t = 0; t < TT; t++) {
        red[j] = so[t][j] * aw;
        __syncthreads();
        for (int off = 64; off > 0; off >>= 1) {
            if (j < off) red[j] += red[j + off];
            __syncthreads();
        }
        if (j == 0) sc[t] = tanhf(red[0] + attn_b[0]);
        __syncthreads();
    }
    if (j == 0) {
        float mx = sc[0];
        for (int t = 1; t < TT; t++) mx = fmaxf(mx, sc[t]);
        float s = 0.f;
        for (int t = 0; t < TT; t++) { w8[t] = expf(sc[t] - mx); s += w8[t]; }
        float inv = 1.f / s;
        for (int t = 0; t < TT; t++) w8[t] *= inv;
    }
    __syncthreads();
    float rep = 0.f;
#pragma unroll
    for (int t = 0; t < TT; t++) rep = fmaf(w8[t], so[t][j], rep);
    red[j] = rep;
    __syncthreads();
    if (j < 16) {
        float s = pb1[j];
        for (int k = 0; k < HH; k++) s = fmaf(red[k], pw1[k * 16 + j], s);
        hm[j] = fmaxf(s, 0.f);
    }
    __syncthreads();
    if (j == 0) {
        float p = pb2[0];
#pragma unroll
        for (int k = 0; k < 16; k++) p = fmaf(hm[k], pw2[k], p);
        out[b] = p;
    }
    if (j < TT) out[BB + b * TT + j] = w8[j];
}

// ------------------------- launch -------------------------
extern "C" void kernel_launch(void* const* d_in, const int* in_sizes, int n_in,
                              void* d_out, int out_size)
{
    const float* x       = (const float*)d_in[0];
    const void*  ei      = d_in[1];
    const void*  ti      = d_in[2];
    const float* proj_w  = (const float*)d_in[3];
    const float* proj_b  = (const float*)d_in[4];
    const float* gcn_w1  = (const float*)d_in[5];
    const float* gcn_b1  = (const float*)d_in[6];
    const float* gcn_w2  = (const float*)d_in[7];
    const float* gcn_b2  = (const float*)d_in[8];
    const float* gru_w_ih = (const float*)d_in[9];
    const float* gru_w_hh = (const float*)d_in[10];
    const float* gru_b_ih = (const float*)d_in[11];
    const float* gru_b_hh = (const float*)d_in[12];
    const float* attn_w  = (const float*)d_in[13];
    const float* attn_b  = (const float*)d_in[14];
    const float* pred_w1 = (const float*)d_in[15];
    const float* pred_b1 = (const float*)d_in[16];
    const float* pred_w2 = (const float*)d_in[17];
    const float* pred_b2 = (const float*)d_in[18];
    float* out = (float*)d_out;

    uint32_t *p_pw, *p_pw1, *p_pw2, *p_pwih, *p_pwhh;
    // device symbol addresses not needed: permB writes via template args below

    dim3 g313(1, (NNODE + 127) / 128);
    dim3 gGi(3, (TT * BB + 127) / 128);
    dim3 gGru(3, (BB + 127) / 128);
    const int aggBlocks = (NNODE * 32 + 255) / 256;
    const int agg2Blocks = (BB * 32 + 255) / 256;

    // --- launches ordered so indices 3 and 5 are big GEMMs (for ncu capture) ---
    k_permB<false><<<(256 * 128 + 255) / 256, 256>>>(proj_w, g_pw, 256, 128);     // 0
    k_permB<false><<<(128 * 128 + 255) / 256, 256>>>(gcn_w1, g_pw1, 128, 128);    // 1
    k_detect<<<1, 1024>>>((const unsigned int*)ei, BB);                           // 2
    tfgemm<256, 0, 1, 0, true, true><<<g313, 256>>>(x, g_pw, proj_b, NNODE);      // 3: proj t=0
    k_cvt_ti<<<(BB + 255) / 256, 256>>>(ti);                                      // 4
    tfgemm<128, 1, 2, 0, false, false><<<g313, 256>>>(nullptr, g_pw1, nullptr, NNODE); // 5: gemm1 t=0
    k_cvt_edges<<<(NE + 255) / 256, 256>>>(ei);                                   // 6

    // remaining preprocessing
    k_permB<false><<<(128 * 128 + 255) / 256, 256>>>(gcn_w2, g_pw2, 128, 128);
    k_permB<true><<<(256 * 384 + 255) / 256, 256>>>(gru_w_ih, g_pwih, 256, 384);
    k_permB<true><<<(128 * 384 + 255) / 256, 256>>>(gru_w_hh, g_pwhh, 128, 384);
    k_init_deg<<<(NNODE + 255) / 256, 256>>>();
    k_deg_edges<<<(NE + 255) / 256, 256>>>();
    k_dinv<<<(NNODE + 255) / 256, 256>>>();
    k_scan<<<1, 1024>>>();
    k_selfloop<<<(NNODE + 255) / 256, 256>>>();
    k_fill_edges<<<(NE + 255) / 256, 256>>>();
    k_clear_masks<<<(NNODE + 255) / 256, 256>>>();
    k_mark_t<<<(BB + 255) / 256, 256>>>();
    k_mark_s<<<(NE + 255) / 256, 256>>>();
    k_mark_s2<<<(NNODE + 255) / 256, 256>>>();
    k_compact<<<(NNODE + 255) / 256, 256>>>();
    k_zero_h0<<<(BB * HH + 255) / 256, 256>>>();

    for (int t = 0; t < TT; t++) {
        if (t > 0) {
            const float* xt = x + (size_t)t * NNODE * FF;
            tfgemm<256, 0, 1, 0, true, true><<<g313, 256>>>(xt, g_pw, proj_b, NNODE);
            tfgemm<128, 1, 2, 0, false, false><<<g313, 256>>>(nullptr, g_pw1, nullptr, NNODE);
        }
        // h1 = relu(agg(m) + b1) over full graph
        k_agg1<<<aggBlocks, 256>>>(gcn_b1);
        // compact h1 rows of target in-neighborhood
        k_gather_hc<<<aggBlocks, 256>>>();
        // mc = hc @ gcn_w2 (Ns rows)
        tfgemm<128, 2, 3, 1, false, false><<<g313, 256>>>(nullptr, g_pw2, nullptr, 0);
        // h2 at target nodes only
        k_agg2t<<<agg2Blocks, 256>>>(gcn_b2);
        // gather targets into tgt[t]
        k_gather<<<BB, 256>>>(t);
    }

    // GI = tgt (8192 x 256) @ wih^T (256 x 384) + b_ih
    tfgemm<256, 3, 4, 0, false, true><<<gGi, 256>>>(nullptr, g_pwih, gru_b_ih, TT * BB);

    for (int t = 0; t < TT; t++) {
        // Gh = h @ whh^T + b_hh  (1024 x 384)
        tfgemm<128, 4, 5, 0, false, true><<<gGru, 256>>>(nullptr, g_pwhh, gru_b_hh, BB);
        k_gru_pt<<<(BB * HH + 255) / 256, 256>>>(t);
    }

    k_final<<<BB, HH>>>(attn_w, attn_b, pred_w1, pred_b1, pred_w2, pred_b2, out);
}